// round 6
// baseline (speedup 1.0000x reference)
#include <cuda_runtime.h>
#include <cuda_fp16.h>
#include <cstdint>

#define USER_NUM 100000
#define ITEM_NUM 50000
#define N_NODES  150000
#define NNZ      4800000
#define EMB      64
#define EPSV     0.2f
#define NORM_EPS 1e-12f

#define SCAN_TILE   1024
#define SCAN_BLOCKS ((N_NODES + SCAN_TILE - 1) / SCAN_TILE)  // 147

// ---- scratch (allocation-free) ----
__device__ alignas(16) int    g_cnt[N_NODES];
__device__ alignas(16) int    g_rowptr[N_NODES];
__device__ alignas(16) int    g_woff[N_NODES];
__device__              int   g_bsum[SCAN_BLOCKS];
__device__ alignas(16) int2   g_pack[NNZ];                     // (col, val-bits)
__device__ alignas(256) __half g_e0[(size_t)N_NODES * EMB];    // fp16 layer state
__device__ alignas(256) __half g_e1[(size_t)N_NODES * EMB];
__device__ alignas(256) float  g_acc[(size_t)N_NODES * EMB];   // fp32 running sum

// ---- counting sort: histogram ----
__global__ void __launch_bounds__(256)
count_kernel(const int* __restrict__ rows)
{
    int i = blockIdx.x * blockDim.x + threadIdx.x;
    if (i < NNZ) atomicAdd(&g_cnt[rows[i]], 1);
}

// ---- scan stage 1 ----
__global__ void __launch_bounds__(256)
scan1_kernel()
{
    __shared__ int sh[256];
    int tid  = threadIdx.x;
    int base = blockIdx.x * SCAN_TILE + tid * 4;

    int v0 = 0, v1 = 0, v2 = 0, v3 = 0;
    if (base + 3 < N_NODES) {
        int4 t = *reinterpret_cast<const int4*>(&g_cnt[base]);
        v0 = t.x; v1 = t.y; v2 = t.z; v3 = t.w;
    } else {
        if (base + 0 < N_NODES) v0 = g_cnt[base + 0];
        if (base + 1 < N_NODES) v1 = g_cnt[base + 1];
        if (base + 2 < N_NODES) v2 = g_cnt[base + 2];
        if (base + 3 < N_NODES) v3 = g_cnt[base + 3];
    }
    int s = v0 + v1 + v2 + v3;
    sh[tid] = s;
    __syncthreads();
    #pragma unroll
    for (int o = 1; o < 256; o <<= 1) {
        int t = (tid >= o) ? sh[tid - o] : 0;
        __syncthreads();
        sh[tid] += t;
        __syncthreads();
    }
    int excl = sh[tid] - s;
    if (base + 0 < N_NODES) g_rowptr[base + 0] = excl;
    excl += v0;
    if (base + 1 < N_NODES) g_rowptr[base + 1] = excl;
    excl += v1;
    if (base + 2 < N_NODES) g_rowptr[base + 2] = excl;
    excl += v2;
    if (base + 3 < N_NODES) g_rowptr[base + 3] = excl;
    if (tid == 255) g_bsum[blockIdx.x] = sh[255];
}

// ---- scan stage 2 ----
__global__ void __launch_bounds__(256)
scan2_kernel()
{
    __shared__ int sh[256];
    int tid = threadIdx.x;
    int v = (tid < SCAN_BLOCKS) ? g_bsum[tid] : 0;
    sh[tid] = v;
    __syncthreads();
    #pragma unroll
    for (int o = 1; o < 256; o <<= 1) {
        int t = (tid >= o) ? sh[tid - o] : 0;
        __syncthreads();
        sh[tid] += t;
        __syncthreads();
    }
    if (tid < SCAN_BLOCKS) g_bsum[tid] = sh[tid] - v;
}

// ---- scan stage 3 ----
__global__ void __launch_bounds__(256)
scan3_kernel()
{
    int i = blockIdx.x * blockDim.x + threadIdx.x;
    if (i < N_NODES) {
        int r = g_rowptr[i] + g_bsum[i / SCAN_TILE];
        g_rowptr[i] = r;
        g_woff[i]   = r;
    }
}

// ---- counting sort: scatter packed (col, val) ----
__global__ void __launch_bounds__(256)
scatter_kernel(const int* __restrict__ rows, const int* __restrict__ cols,
               const float* __restrict__ vals)
{
    int i = blockIdx.x * blockDim.x + threadIdx.x;
    if (i < NNZ) {
        int p = atomicAdd(&g_woff[rows[i]], 1);
        g_pack[p] = make_int2(cols[i], __float_as_int(vals[i]));
    }
}

// ---- init: ego(0) = concat(user, item) quantized to fp16 ----
__global__ void __launch_bounds__(256)
init_kernel(const float* __restrict__ user, const float* __restrict__ item,
            __half* __restrict__ e0)
{
    int i = blockIdx.x * blockDim.x + threadIdx.x;             // half2 index
    const int total = N_NODES * EMB / 2;
    if (i >= total) return;
    const int usplit = USER_NUM * EMB / 2;
    float2 v = (i < usplit)
        ? __ldg(reinterpret_cast<const float2*>(user) + i)
        : __ldg(reinterpret_cast<const float2*>(item) + (i - usplit));
    reinterpret_cast<__half2*>(e0)[i] = __float22half2_rn(v);
}

// unpack 16B of fp16 (8 dims) and fma into 8 fp32 accumulators
__device__ __forceinline__ void fma8(uint4 q, float v, float* a)
{
    float2 f0 = __half22float2(*reinterpret_cast<__half2*>(&q.x));
    float2 f1 = __half22float2(*reinterpret_cast<__half2*>(&q.y));
    float2 f2 = __half22float2(*reinterpret_cast<__half2*>(&q.z));
    float2 f3 = __half22float2(*reinterpret_cast<__half2*>(&q.w));
    a[0] = fmaf(v, f0.x, a[0]); a[1] = fmaf(v, f0.y, a[1]);
    a[2] = fmaf(v, f1.x, a[2]); a[3] = fmaf(v, f1.y, a[3]);
    a[4] = fmaf(v, f2.x, a[4]); a[5] = fmaf(v, f2.y, a[5]);
    a[6] = fmaf(v, f3.x, a[6]); a[7] = fmaf(v, f3.y, a[7]);
}

// ---- fused CSR SpMM: warp per row, FOUR 8-lane nnz streams.
// Each lane loads uint4 (16B = 8 fp16 dims): one LDG.128 covers 4 nnz.
// Pack loads: lane loads g_pack[idx + stream] -> coalesced 32B broadcast.
// Stream partials merged with shfl_xor(8,16). Epilogue fused. ----
__global__ void __launch_bounds__(256)
spmm_fused(const __half* __restrict__ x, const float* __restrict__ noise,
           __half* __restrict__ dst, float* __restrict__ acc,
           float* __restrict__ out, int k)
{
    int warp = (int)((blockIdx.x * (unsigned)blockDim.x + threadIdx.x) >> 5);
    int lane = threadIdx.x & 31;
    if (warp >= N_NODES) return;

    int s = lane >> 3;          // nnz stream (0..3)
    int d = lane & 7;           // dim chunk: dims [8d, 8d+8)

    int start = __ldg(&g_rowptr[warp]);
    int end   = (warp + 1 < N_NODES) ? __ldg(&g_rowptr[warp + 1]) : NNZ;

    const uint4* __restrict__ xq = reinterpret_cast<const uint4*>(x); // row = 8 uint4

    float a[8];
    #pragma unroll
    for (int i = 0; i < 8; i++) a[i] = 0.f;

    int idx = start;
    // 2x unrolled: 8 nnz per iteration, 2 pack LDGs + 2 gather LDGs
    for (; idx + 8 <= end; idx += 8) {
        int2 p0 = __ldg(&g_pack[idx + s]);
        int2 p1 = __ldg(&g_pack[idx + 4 + s]);
        uint4 q0 = __ldg(xq + (size_t)p0.x * 8 + d);
        uint4 q1 = __ldg(xq + (size_t)p1.x * 8 + d);
        fma8(q0, __int_as_float(p0.y), a);
        fma8(q1, __int_as_float(p1.y), a);
    }
    for (; idx < end; idx += 4) {
        if (idx + s < end) {
            int2 p = __ldg(&g_pack[idx + s]);
            uint4 q = __ldg(xq + (size_t)p.x * 8 + d);
            fma8(q, __int_as_float(p.y), a);
        }
    }

    // merge the four nnz streams: every lane ends with full sums for its dims
    #pragma unroll
    for (int i = 0; i < 8; i++) {
        a[i] += __shfl_xor_sync(0xffffffffu, a[i], 8);
        a[i] += __shfl_xor_sync(0xffffffffu, a[i], 16);
    }

    // epilogue: e = s + sign(s) * l2_normalize(noise_row) * eps
    const float4* nz = reinterpret_cast<const float4*>(noise + (size_t)warp * EMB + d * 8);
    float4 r0 = __ldg(nz);
    float4 r1 = __ldg(nz + 1);
    float rr[8] = {r0.x, r0.y, r0.z, r0.w, r1.x, r1.y, r1.z, r1.w};

    float ss = 0.f;
    #pragma unroll
    for (int i = 0; i < 8; i++) ss += rr[i] * rr[i];
    ss += __shfl_xor_sync(0xffffffffu, ss, 1);
    ss += __shfl_xor_sync(0xffffffffu, ss, 2);
    ss += __shfl_xor_sync(0xffffffffu, ss, 4);
    float scale = EPSV / fmaxf(sqrtf(ss), NORM_EPS);

    float e[8];
    #pragma unroll
    for (int i = 0; i < 8; i++) {
        float sv = a[i];
        e[i] = sv + (sv > 0.f ? scale * rr[i] : (sv < 0.f ? -scale * rr[i] : 0.f));
    }

    if (s != 0) return;  // streams 1-3 hold duplicates; stream 0 writes

    if (k < 2) {
        uint4 hp;
        __half2 h0 = __float22half2_rn(make_float2(e[0], e[1]));
        __half2 h1 = __float22half2_rn(make_float2(e[2], e[3]));
        __half2 h2 = __float22half2_rn(make_float2(e[4], e[5]));
        __half2 h3 = __float22half2_rn(make_float2(e[6], e[7]));
        hp.x = *reinterpret_cast<unsigned int*>(&h0);
        hp.y = *reinterpret_cast<unsigned int*>(&h1);
        hp.z = *reinterpret_cast<unsigned int*>(&h2);
        hp.w = *reinterpret_cast<unsigned int*>(&h3);
        reinterpret_cast<uint4*>(dst)[(size_t)warp * 8 + d] = hp;
    }

    size_t q = (size_t)warp * 16 + (size_t)d * 2;  // float4 index
    float4 e0v = make_float4(e[0], e[1], e[2], e[3]);
    float4 e1v = make_float4(e[4], e[5], e[6], e[7]);

    if (k == 0) {
        reinterpret_cast<float4*>(acc)[q]     = e0v;
        reinterpret_cast<float4*>(acc)[q + 1] = e1v;
    } else if (k == 1) {
        float4 a0 = reinterpret_cast<const float4*>(acc)[q];
        float4 a1 = reinterpret_cast<const float4*>(acc)[q + 1];
        a0.x += e0v.x; a0.y += e0v.y; a0.z += e0v.z; a0.w += e0v.w;
        a1.x += e1v.x; a1.y += e1v.y; a1.z += e1v.z; a1.w += e1v.w;
        reinterpret_cast<float4*>(acc)[q]     = a0;
        reinterpret_cast<float4*>(acc)[q + 1] = a1;
    } else {
        float4 a0 = reinterpret_cast<const float4*>(acc)[q];
        float4 a1 = reinterpret_cast<const float4*>(acc)[q + 1];
        float4 o0, o1;
        o0.x = (a0.x + e0v.x) * (1.0f / 3.0f);
        o0.y = (a0.y + e0v.y) * (1.0f / 3.0f);
        o0.z = (a0.z + e0v.z) * (1.0f / 3.0f);
        o0.w = (a0.w + e0v.w) * (1.0f / 3.0f);
        o1.x = (a1.x + e1v.x) * (1.0f / 3.0f);
        o1.y = (a1.y + e1v.y) * (1.0f / 3.0f);
        o1.z = (a1.z + e1v.z) * (1.0f / 3.0f);
        o1.w = (a1.w + e1v.w) * (1.0f / 3.0f);
        reinterpret_cast<float4*>(out)[q]     = o0;
        reinterpret_cast<float4*>(out)[q + 1] = o1;
    }
}

extern "C" void kernel_launch(void* const* d_in, const int* in_sizes, int n_in,
                              void* d_out, int out_size)
{
    const float* user  = (const float*)d_in[0];
    const float* item  = (const float*)d_in[1];
    const int*   rows  = (const int*)  d_in[2];
    const int*   cols  = (const int*)  d_in[3];
    const float* vals  = (const float*)d_in[4];
    const float* noise = (const float*)d_in[5];
    float*       out   = (float*)d_out;

    __half *e0, *e1;
    float  *acc;
    int    *cnt;
    cudaGetSymbolAddress((void**)&e0,  g_e0);
    cudaGetSymbolAddress((void**)&e1,  g_e1);
    cudaGetSymbolAddress((void**)&acc, g_acc);
    cudaGetSymbolAddress((void**)&cnt, g_cnt);

    // ---- build row-sorted packed CSR (rebuilt every call) ----
    cudaMemsetAsync(cnt, 0, (size_t)N_NODES * sizeof(int));
    count_kernel  <<<(NNZ + 255) / 256, 256>>>(rows);
    scan1_kernel  <<<SCAN_BLOCKS, 256>>>();
    scan2_kernel  <<<1, 256>>>();
    scan3_kernel  <<<(N_NODES + 255) / 256, 256>>>();
    scatter_kernel<<<(NNZ + 255) / 256, 256>>>(rows, cols, vals);

    // ---- ego(0) = concat(user, item) in fp16 ----
    init_kernel<<<(N_NODES * EMB / 2 + 255) / 256, 256>>>(user, item, e0);

    const int fused_blocks = (N_NODES + 7) / 8;  // warp per row

    spmm_fused<<<fused_blocks, 256>>>(e0, noise + 0ull * N_NODES * EMB, e1, acc, out, 0);
    spmm_fused<<<fused_blocks, 256>>>(e1, noise + 1ull * N_NODES * EMB, e0, acc, out, 1);
    spmm_fused<<<fused_blocks, 256>>>(e0, noise + 2ull * N_NODES * EMB, e1, acc, out, 2);
}